// round 11
// baseline (speedup 1.0000x reference)
#include <cuda_runtime.h>
#include <math.h>

#define GN 256
#define NVOX (GN*GN*GN)          // 2^24
#define MAX_ID 32
#define NUM_CLASSES 13
#define NBINS ((MAX_ID+1)*NUM_CLASSES)   // 429
#define LUT_SZ (MAX_ID+3)                // 35
#define KEY_WALL  33
#define KEY_FLOOR 34
#define SURF_BIT  0x80

// ---------------- device scratch (no allocations allowed) ----------------
__device__ int           g_counts[NBINS];
__device__ int           g_sem_lut[LUT_SZ];
__device__ unsigned char g_keylut[256];   // key byte -> panoptic label (bit7 ignored)
__device__ unsigned char g_key[NVOX];     // bit7=surface, low bits: 33=wall,34=floor,else inst

__device__ const float* g_geo;
__device__ const int*   g_inst;
__device__ const int*   g_sem;

// ---------------- kernel A: classify big buffers by content (3 warps) ----------------
__global__ void classifyK(const int* a, const int* b, const int* c) {
    __shared__ int smax[3];
    const int* bufs[3] = { a, b, c };
    int w = threadIdx.x >> 5, lane = threadIdx.x & 31;
    if (w < 3) {
        const int* p = bufs[w];
        int mx = -2147483647;
        for (int i = lane; i < 2048; i += 32) {
            int v = p[i * 769];
            mx = v > mx ? v : mx;
        }
        for (int o = 16; o > 0; o >>= 1) {
            int t = __shfl_xor_sync(0xFFFFFFFFu, mx, o);
            mx = t > mx ? t : mx;
        }
        if (lane == 0) smax[w] = mx;
    }
    __syncthreads();
    if (threadIdx.x == 0) {
        bool used[3] = { false, false, false };
        bool gs = false, ss = false, is = false;
        for (int t = 0; t < 3; t++)
            if (!used[t] && (smax[t] > 1000000 || smax[t] < 0)) {
                g_geo = (const float*)bufs[t]; used[t] = true; gs = true; break;
            }
        for (int t = 0; t < 3; t++)
            if (!used[t] && smax[t] < 13) {
                g_sem = bufs[t]; used[t] = true; ss = true; break;
            }
        for (int t = 0; t < 3; t++)
            if (!used[t]) { g_inst = bufs[t]; used[t] = true; is = true; break; }
        if (!gs) g_geo  = (const float*)a;
        if (!ss) g_sem  = c;
        if (!is) g_inst = b;
    }
    for (int i = threadIdx.x; i < NBINS; i += blockDim.x) g_counts[i] = 0;
}

// ---------------- kernel 1: joint histogram + key-grid (surface bit folded in) ----------------
__global__ void histK() {
    __shared__ int sc[NBINS];
    for (int i = threadIdx.x; i < NBINS; i += blockDim.x) sc[i] = 0;
    __syncthreads();

    const int4*   inst4 = (const int4*)g_inst;
    const int4*   sem4  = (const int4*)g_sem;
    const float4* geo4  = (const float4*)g_geo;
    uchar4*       key4  = (uchar4*)g_key;
    int stride = gridDim.x * blockDim.x;
    int n4 = NVOX / 4;
    for (int i = blockIdx.x * blockDim.x + threadIdx.x; i < n4; i += stride) {
        int4   v = inst4[i];
        int4   s = sem4[i];
        float4 g = geo4[i];
        unsigned ix;
        ix = (unsigned)(v.x * NUM_CLASSES + s.x); if (ix < NBINS) atomicAdd(&sc[ix], 1);
        ix = (unsigned)(v.y * NUM_CLASSES + s.y); if (ix < NBINS) atomicAdd(&sc[ix], 1);
        ix = (unsigned)(v.z * NUM_CLASSES + s.z); if (ix < NBINS) atomicAdd(&sc[ix], 1);
        ix = (unsigned)(v.w * NUM_CLASSES + s.w); if (ix < NBINS) atomicAdd(&sc[ix], 1);
        uchar4 k;
        k.x = ((s.x == 10) ? KEY_WALL : ((s.x == 11) ? KEY_FLOOR : (unsigned char)(v.x & 31)))
            | (fabsf(g.x) <= 1.5f ? SURF_BIT : 0);
        k.y = ((s.y == 10) ? KEY_WALL : ((s.y == 11) ? KEY_FLOOR : (unsigned char)(v.y & 31)))
            | (fabsf(g.y) <= 1.5f ? SURF_BIT : 0);
        k.z = ((s.z == 10) ? KEY_WALL : ((s.z == 11) ? KEY_FLOOR : (unsigned char)(v.z & 31)))
            | (fabsf(g.z) <= 1.5f ? SURF_BIT : 0);
        k.w = ((s.w == 10) ? KEY_WALL : ((s.w == 11) ? KEY_FLOOR : (unsigned char)(v.w & 31)))
            | (fabsf(g.w) <= 1.5f ? SURF_BIT : 0);
        key4[i] = k;
    }
    __syncthreads();
    for (int i = threadIdx.x; i < NBINS; i += blockDim.x)
        if (sc[i]) atomicAdd(&g_counts[i], sc[i]);
}

// ---------------- kernel 2: build LUTs (tiny, 1 thread) ----------------
__global__ void lutK(const int* __restrict__ ids2d, int n2d) {
    bool in2d[MAX_ID + 1];
    for (int i = 0; i <= MAX_ID; i++) in2d[i] = false;
    for (int t = 0; t < n2d; t++) {
        int v = ids2d[t] + 1;
        if (v >= 1 && v <= MAX_ID) in2d[v] = true;
    }
    int hist[MAX_ID + 1];
    for (int i = 0; i <= MAX_ID; i++) {
        int h = 0;
        for (int c = 0; c < NUM_CLASSES; c++) h += g_counts[i * NUM_CLASSES + c];
        hist[i] = h;
    }
    int zero_present = 0;
    for (int i = 0; i <= MAX_ID; i++)
        if (hist[i] > 0 && !in2d[i]) zero_present = 1;

    bool present[MAX_ID + 1];
    int  pano_ids[MAX_ID + 1];
    int  pano_lut[MAX_ID + 1];
    int rank = 0;
    pano_lut[0] = 0;
    for (int i = 1; i <= MAX_ID; i++) {
        present[i] = in2d[i] && (hist[i] > 0);
        if (present[i]) rank++;
        pano_ids[i] = present[i] ? (rank - 1 + zero_present + 2) : 0;
        pano_lut[i] = pano_ids[i];
    }
    int sel_label[MAX_ID + 1];
    for (int i = 1; i <= MAX_ID; i++) {
        int best = -2147483647, bi = 0;
        for (int c = 0; c < NUM_CLASSES; c++) {
            int v = (c == 0 || c == 10 || c == 11) ? -1 : g_counts[i * NUM_CLASSES + c];
            if (v > best) { best = v; bi = c; }
        }
        sel_label[i] = bi;
    }
    for (int k = 0; k < LUT_SZ; k++) g_sem_lut[k] = 0;
    g_sem_lut[1] = 10;
    g_sem_lut[2] = 11;
    for (int i = 1; i <= MAX_ID; i++) {
        int idx = pano_ids[i];
        int val = present[i] ? sel_label[i] : 0;
        if (idx >= 0 && idx < LUT_SZ) g_sem_lut[idx] = val;
    }
    // key byte -> panoptic label (bit7 = surface flag, ignored for label)
    for (int t = 0; t < 256; t++) {
        int base = t & 0x7F;
        unsigned char val = 0;
        if (base < 32)            val = (unsigned char)pano_lut[base];
        else if (base == KEY_WALL)  val = 1;
        else if (base == KEY_FLOOR) val = 2;
        g_keylut[t] = val;
    }
}

// ---------------- kernel 3: nn_search over keys + float4 outputs ----------------
__global__ void nnK(float* __restrict__ out, long long out_elems) {
    __shared__ unsigned char lut[256];
    __shared__ float slut[LUT_SZ];
    if (threadIdx.x < 256) lut[threadIdx.x] = g_keylut[threadIdx.x];
    if (threadIdx.x < LUT_SZ) slut[threadIdx.x] = (float)g_sem_lut[threadIdx.x];
    __syncthreads();

    int t = blockIdx.x * blockDim.x + threadIdx.x;   // 4 voxels per thread
    int n4 = NVOX / 4;
    if (t >= n4) return;
    int base = t * 4;

    uchar4 k4 = ((const uchar4*)g_key)[t];
    int keys[4] = { k4.x, k4.y, k4.z, k4.w };
    int lab[4];

    #pragma unroll
    for (int q = 0; q < 4; q++) {
        int key = keys[q];
        int label = lut[key];
        if (label == 0 && (key & SURF_BIT)) {
            int idx = base + q;
            int k = idx & 255;
            int j = (idx >> 8) & 255;
            int i = idx >> 16;
            // lexicographic offsets di,dj,dk in [-3,3); first positive neighbor wins
            #pragma unroll 1
            for (int di = -3; di < 3 && !label; di++) {
                int ii = (i + di) & 255;
                #pragma unroll 1
                for (int dj = -3; dj < 3 && !label; dj++) {
                    int jj = (j + dj) & 255;
                    const unsigned char* row = &g_key[(ii << 16) | (jj << 8)];
                    #pragma unroll
                    for (int dk = -3; dk < 3; dk++) {
                        int v = lut[row[(k + dk) & 255]];
                        if (v > 0) { label = v; break; }
                    }
                }
            }
        }
        lab[q] = label;
    }

    float4 po = make_float4((float)lab[0], (float)lab[1], (float)lab[2], (float)lab[3]);
    float4 so = make_float4(slut[lab[0]], slut[lab[1]], slut[lab[2]], slut[lab[3]]);

    if ((long long)base + 3 < out_elems)
        ((float4*)out)[t] = po;
    if ((long long)base + NVOX + 3 < out_elems)
        ((float4*)(out + NVOX))[t] = so;
}

// ---------------- launch ----------------
extern "C" void kernel_launch(void* const* d_in, const int* in_sizes, int n_in,
                              void* d_out, int out_size) {
    const int* big[3] = { 0, 0, 0 };
    const int* ids2d = 0;
    int n2d = 0, nb = 0;
    for (int t = 0; t < n_in; t++) {
        if (in_sizes[t] < 1024) { ids2d = (const int*)d_in[t]; n2d = in_sizes[t]; }
        else if (nb < 3)        { big[nb++] = (const int*)d_in[t]; }
    }

    float* out = (float*)d_out;
    long long out_elems = (long long)out_size;

    classifyK<<<1, 128>>>(big[0], big[1], big[2]);
    histK<<<2048, 256>>>();
    if (ids2d) lutK<<<1, 1>>>(ids2d, n2d);
    nnK<<<(NVOX / 4 + 255) / 256, 256>>>(out, out_elems);
}